// round 5
// baseline (speedup 1.0000x reference)
#include <cuda_runtime.h>
#include <math.h>

#define NTOK 32768
#define CFEAT 64
#define NSPLIT 8
#define NBLK 148          // persistent grid: one block per SM, all resident

// ---------------- scratch (static device memory; no allocation) ----------------
__device__ float g_t  [NTOK * CFEAT];   // tokens [n][c]
__device__ float g_hT [NTOK * CFEAT];   // channel-major [c][n]
__device__ float g_qs [NTOK * CFEAT];
__device__ float g_ks [NTOK * CFEAT];
__device__ float g_vs [NTOK * CFEAT];
__device__ int   g_idx3[3 * NTOK];
__device__ int   g_M3[3];
__device__ float g_part[(NTOK / 32) * NSPLIT * 32 * 68];
__device__ unsigned g_gen = 0;          // barrier generation (monotonic, wraps ok)
__device__ unsigned g_arrive = 0;       // barrier arrival count (self-restoring)

// ---------------- software grid barrier (all NBLK blocks resident) -------------
__device__ __forceinline__ void grid_bar()
{
    __syncthreads();
    if (threadIdx.x == 0) {
        __threadfence();
        unsigned gen = g_gen;
        if (atomicAdd(&g_arrive, 1u) == NBLK - 1) {
            g_arrive = 0;
            __threadfence();
            atomicAdd(&g_gen, 1u);
        } else {
            while (atomicAdd(&g_gen, 0u) == gen) __nanosleep(64);
        }
        __threadfence();
    }
    __syncthreads();
}

// ---------------- fused patch conv + pos embed, dual-layout write --------------
__global__ void __launch_bounds__(256) conv_pos_kernel(
    const float* __restrict__ x,
    const float* __restrict__ W,    // [64][64]
    const float* __restrict__ b,
    const float* __restrict__ pos)  // [64][32768]
{
    __shared__ float P[32][68];
    __shared__ float O[64][33];
    int n0  = blockIdx.x * 32;
    int tid = threadIdx.x;

    #pragma unroll
    for (int j = 0; j < 8; ++j) {
        int e   = tid + 256 * j;
        int tok = e >> 6, k = e & 63;
        int n = n0 + tok;
        int z = n >> 10, y = (n >> 5) & 31, xx = n & 31;
        int dz = k >> 4, dy = (k >> 2) & 3, dx = k & 3;
        P[tok][k] = x[(4*z + dz) * 16384 + (4*y + dy) * 128 + (4*xx + dx)];
    }
    __syncthreads();

    int c = tid >> 2, sub = tid & 3;
    float w[64];
    {
        const float4* wp = (const float4*)(W + c * 64);
        #pragma unroll
        for (int i = 0; i < 16; ++i) {
            float4 t4 = wp[i];
            w[4*i] = t4.x; w[4*i+1] = t4.y; w[4*i+2] = t4.z; w[4*i+3] = t4.w;
        }
    }
    float bv = b[c];
    float acc[8];
    #pragma unroll
    for (int u = 0; u < 8; ++u) acc[u] = bv;

    #pragma unroll
    for (int k4 = 0; k4 < 16; ++k4) {
        #pragma unroll
        for (int u = 0; u < 8; ++u) {
            float4 p = *(const float4*)&P[u * 4 + sub][k4 * 4];
            acc[u] += p.x * w[4*k4];
            acc[u] += p.y * w[4*k4+1];
            acc[u] += p.z * w[4*k4+2];
            acc[u] += p.w * w[4*k4+3];
        }
    }
    #pragma unroll
    for (int u = 0; u < 8; ++u) O[c][u * 4 + sub] = acc[u];
    __syncthreads();

    #pragma unroll
    for (int j = 0; j < 8; ++j) {
        int e  = tid + 256 * j;
        int cc = e >> 5, nl = e & 31;
        float v = O[cc][nl] + pos[cc * NTOK + n0 + nl];
        O[cc][nl] = v;
        g_hT[cc * NTOK + n0 + nl] = v;
    }
    __syncthreads();

    #pragma unroll
    for (int j = 0; j < 8; ++j) {
        int e  = tid + 256 * j;
        int nl = e >> 6, cc = e & 63;
        g_t[(n0 + nl) * 64 + cc] = O[cc][nl];
    }
}

// =================== persistent fused attention stack ==========================
// grid = NBLK blocks x 512 threads. Stages separated by grid_bar():
//   idx(3 dil) | [qkv | part | combine] x 3
__global__ void __launch_bounds__(512) fused_attn_kernel(
    const float* __restrict__ qkvw0, const float* __restrict__ qkvb0,
    const float* __restrict__ pw0,   const float* __restrict__ pb0,
    const float* __restrict__ qkvw1, const float* __restrict__ qkvb1,
    const float* __restrict__ pw1,   const float* __restrict__ pb1,
    const float* __restrict__ qkvw2, const float* __restrict__ qkvb2,
    const float* __restrict__ pw2,   const float* __restrict__ pb2)
{
    __shared__ float SM[160 * 68];            // 43.5 KB, re-aliased per stage
    __shared__ int   scan[512];

    int tid = threadIdx.x;
    int bid = blockIdx.x;

    // ---------------- stage 0: dilation index build (blocks 0..2) --------------
    if (bid < 3) {
        int dil = (bid == 0) ? 2 : (bid == 1) ? 4 : 6;
        int* out = g_idx3 + bid * NTOK;
        float fd = (float)dil;
        int base = tid * 64;

        unsigned long long flags = 0ull; int c = 0;
        for (int j = 0; j < 64; ++j) {
            int n = base + j;
            int z = (n >> 10) - 16, y = ((n >> 5) & 31) - 16, x = (n & 31) - 16;
            int ss = z*z + y*y + x*x;
            float d = sqrtf((float)ss);
            bool ok = (fmodf(d, fd) == 0.0f) || (ss == 0);
            if (ok) { flags |= (1ull << j); c++; }
        }
        scan[tid] = c;
        __syncthreads();
        for (int off = 1; off < 512; off <<= 1) {
            int v = (tid >= off) ? scan[tid - off] : 0;
            __syncthreads();
            scan[tid] += v;
            __syncthreads();
        }
        int pos = scan[tid] - c;
        for (int j = 0; j < 64; ++j)
            if (flags & (1ull << j)) out[pos++] = base + j;
        if (tid == 511) g_M3[bid] = scan[511];
    }
    grid_bar();

    const float* QW[3] = {qkvw0, qkvw1, qkvw2};
    const float* QB[3] = {qkvb0, qkvb1, qkvb2};
    const float* PW[3] = {pw0, pw1, pw2};
    const float* PB[3] = {pb0, pb1, pb2};

    for (int di = 0; di < 3; ++di) {
        int M = g_M3[di];
        const int* __restrict__ idx = g_idx3 + di * NTOK;
        int mtiles = (M + 31) >> 5;

        // ---------------- stage: QKV (scale 1/8 folded into Q) -----------------
        {
            float (*Ts)[68] = (float(*)[68])SM;
            const float* W  = QW[di];
            const float* bb = QB[di];

            int oc   = tid >> 1;          // 0..255 (valid < 192)
            int half = tid & 1;
            float w[64]; float bv = 0.f;
            if (oc < 192) {
                const float4* wr = (const float4*)(W + oc * 64);
                #pragma unroll
                for (int i = 0; i < 16; ++i) {
                    float4 t4 = wr[i];
                    w[4*i] = t4.x; w[4*i+1] = t4.y; w[4*i+2] = t4.z; w[4*i+3] = t4.w;
                }
                bv = bb[oc];
            }

            for (int mt = bid; mt < mtiles; mt += NBLK) {
                int m0 = mt * 32;
                __syncthreads();
                #pragma unroll
                for (int j = 0; j < 4; ++j) {
                    int e = tid + 512 * j;
                    int ml = e >> 6, k = e & 63;
                    int m = m0 + ml;
                    Ts[ml][k] = (m < M) ? g_t[idx[m] * 64 + k] : 0.f;
                }
                __syncthreads();
                if (oc < 192) {
                    int mmax = min(32, M - m0);
                    #pragma unroll
                    for (int g = 0; g < 2; ++g) {
                        int ml0 = half * 16 + g * 8;
                        float acc[8];
                        #pragma unroll
                        for (int u = 0; u < 8; ++u) acc[u] = bv;
                        #pragma unroll
                        for (int k4 = 0; k4 < 16; ++k4) {
                            #pragma unroll
                            for (int u = 0; u < 8; ++u) {
                                float4 t4 = *(const float4*)&Ts[ml0 + u][k4 * 4];
                                acc[u] += t4.x * w[4*k4];
                                acc[u] += t4.y * w[4*k4+1];
                                acc[u] += t4.z * w[4*k4+2];
                                acc[u] += t4.w * w[4*k4+3];
                            }
                        }
                        #pragma unroll
                        for (int u = 0; u < 8; ++u) {
                            int ml = ml0 + u;
                            if (ml < mmax) {
                                int m = m0 + ml;
                                if      (oc <  64) g_qs[m * 64 + oc]       = acc[u] * 0.125f;
                                else if (oc < 128) g_ks[m * 64 + oc - 64]  = acc[u];
                                else               g_vs[m * 64 + oc - 128] = acc[u];
                            }
                        }
                    }
                }
            }
        }
        grid_bar();

        // ---------------- stage: attention partials (split-K) ------------------
        {
            float (*Ksm)[68] = (float(*)[68])SM;
            float (*Vsm)[68] = (float(*)[68])(SM + 64 * 68);
            float (*Psm)[68] = (float(*)[68])(SM + 128 * 68);

            int r  = tid >> 4;        // query row 0..31
            int qq = tid & 15;        // lane in row
            int cb = qq * 4;          // 4 output channels

            int chunk = 64;           // M <= 512 -> ceil(M/512)*64 = 64
            int ntask = mtiles * NSPLIT;

            for (int task = bid; task < ntask; task += NBLK) {
                int mt = task >> 3;
                int s  = task & 7;
                int nb = s * chunk;
                int ne = min(nb + chunk, M);

                int  m0    = mt * 32;
                int  m     = m0 + r;
                bool valid = (m < M);

                float qreg[64];
                {
                    const float4* qp = (const float4*)(g_qs + (valid ? m : m0) * 64);
                    #pragma unroll
                    for (int i = 0; i < 16; ++i) {
                        float4 v = qp[i];
                        qreg[4*i] = v.x; qreg[4*i+1] = v.y;
                        qreg[4*i+2] = v.z; qreg[4*i+3] = v.w;
                    }
                }
                float y[4] = {0.f, 0.f, 0.f, 0.f};
                float row_max = -1e30f, row_sum = 0.f;

                for (int n0 = nb; n0 < ne; n0 += 64) {
                    __syncthreads();
                    #pragma unroll
                    for (int j = 0; j < 2; ++j) {
                        int e = tid + 512 * j;
                        int nl = e >> 4, k4 = e & 15;
                        int n = n0 + nl;
                        float4 kv = make_float4(0.f, 0.f, 0.f, 0.f);
                        float4 vv = kv;
                        if (n < ne) {
                            kv = *(const float4*)(g_ks + n * 64 + k4 * 4);
                            vv = *(const float4*)(g_vs + n * 64 + k4 * 4);
                        }
                        *(float4*)&Ksm[nl][k4 * 4] = kv;
                        *(float4*)&Vsm[nl][k4 * 4] = vv;
                    }
                    __syncthreads();

                    float sc[4];
                    float tmax = -1e30f;
                    #pragma unroll
                    for (int kk = 0; kk < 4; ++kk) {
                        int nl = qq + 16 * kk;
                        float acc = 0.f;
                        #pragma unroll
                        for (int k4 = 0; k4 < 16; ++k4) {
                            float4 kvec = *(const float4*)&Ksm[nl][k4 * 4];
                            acc += qreg[4*k4]   * kvec.x;
                            acc += qreg[4*k4+1] * kvec.y;
                            acc += qreg[4*k4+2] * kvec.z;
                            acc += qreg[4*k4+3] * kvec.w;
                        }
                        if (n0 + nl >= ne) acc = -1e30f;
                        sc[kk] = acc;
                        tmax = fmaxf(tmax, acc);
                    }
                    #pragma unroll
                    for (int o = 1; o < 16; o <<= 1)
                        tmax = fmaxf(tmax, __shfl_xor_sync(0xffffffffu, tmax, o));

                    float nmax = fmaxf(row_max, tmax);
                    float corr = __expf(row_max - nmax);
                    float lsum = 0.f;
                    #pragma unroll
                    for (int kk = 0; kk < 4; ++kk) {
                        float p = __expf(sc[kk] - nmax);
                        Psm[r][qq + 16 * kk] = p;
                        lsum += p;
                    }
                    #pragma unroll
                    for (int o = 1; o < 16; o <<= 1)
                        lsum += __shfl_xor_sync(0xffffffffu, lsum, o);
                    row_sum = row_sum * corr + lsum;
                    row_max = nmax;
                    #pragma unroll
                    for (int j = 0; j < 4; ++j) y[j] *= corr;
                    __syncwarp();

                    for (int nl = 0; nl < 64; ++nl) {
                        float p = Psm[r][nl];
                        float4 v0 = *(const float4*)&Vsm[nl][cb];
                        y[0] += p * v0.x; y[1] += p * v0.y;
                        y[2] += p * v0.z; y[3] += p * v0.w;
                    }
                }

                float* pp = g_part + (((size_t)mt * NSPLIT + s) * 32 + r) * 68;
                *(float4*)(pp + cb) = make_float4(y[0], y[1], y[2], y[3]);
                if (qq == 0) { pp[64] = row_max; pp[65] = row_sum; }
                __syncthreads();
            }
        }
        grid_bar();

        // ---------------- stage: combine + proj + residual + dual scatter ------
        {
            float (*Ysm)[68] = (float(*)[68])SM;
            const float* Wp = PW[di];
            const float* bp = PB[di];

            int r  = tid >> 4;
            int qq = tid & 15;
            int cb = qq * 4;

            int oc = tid & 63;
            int rb = tid >> 6;   // 0..7
            float wrow[64];
            {
                const float4* wr = (const float4*)(Wp + oc * 64);
                #pragma unroll
                for (int i = 0; i < 16; ++i) {
                    float4 v = wr[i];
                    wrow[4*i] = v.x; wrow[4*i+1] = v.y;
                    wrow[4*i+2] = v.z; wrow[4*i+3] = v.w;
                }
            }
            float bv = bp[oc];

            for (int mt = bid; mt < mtiles; mt += NBLK) {
                int m0 = mt * 32;
                const float* pb2 = g_part + ((size_t)mt * NSPLIT) * 32 * 68 + r * 68;

                float gm = -1e30f;
                #pragma unroll
                for (int s = 0; s < NSPLIT; ++s)
                    gm = fmaxf(gm, pb2[s * 32 * 68 + 64]);

                float l = 0.f;
                float y[4] = {0.f, 0.f, 0.f, 0.f};
                #pragma unroll
                for (int s = 0; s < NSPLIT; ++s) {
                    const float* ps = pb2 + s * 32 * 68;
                    float w = __expf(ps[64] - gm);
                    l += w * ps[65];
                    float4 a = *(const float4*)(ps + cb);
                    y[0] += w * a.x; y[1] += w * a.y;
                    y[2] += w * a.z; y[3] += w * a.w;
                }
                float inv = 1.0f / l;
                __syncthreads();
                *(float4*)&Ysm[r][cb] =
                    make_float4(y[0]*inv, y[1]*inv, y[2]*inv, y[3]*inv);
                __syncthreads();

                int mmax = min(32, M - m0);
                for (int rr = rb; rr < mmax; rr += 8) {
                    float a0 = bv;
                    #pragma unroll
                    for (int k4 = 0; k4 < 16; ++k4) {
                        float4 y0 = *(const float4*)&Ysm[rr][k4 * 4];
                        a0 += y0.x * wrow[4*k4];
                        a0 += y0.y * wrow[4*k4+1];
                        a0 += y0.z * wrow[4*k4+2];
                        a0 += y0.w * wrow[4*k4+3];
                    }
                    a0 += Ysm[rr][oc];
                    int tok = idx[m0 + rr];
                    g_t [tok * 64 + oc]   = a0;
                    g_hT[oc * NTOK + tok] = a0;
                }
            }
        }
        if (di < 2) grid_bar();
    }
}

// ---------------- trilinear x4 upsample: hT[c][32^3] -> out[c][128^3] ----------
__global__ void __launch_bounds__(256) upsample_kernel(float* __restrict__ out)
{
    const float S = 31.0f / 127.0f;
    int zo  = blockIdx.x;
    int c   = blockIdx.y;
    int tid = threadIdx.x;

    float pz = (float)zo * S;
    int z0 = (int)pz;
    int z1 = min(z0 + 1, 31);
    float wz = pz - (float)z0;

    __shared__ float F[1024];
    __shared__ float R[128][33];

    const float* p0 = g_hT + c * NTOK + z0 * 1024;
    const float* p1 = g_hT + c * NTOK + z1 * 1024;
    #pragma unroll
    for (int j = 0; j < 4; ++j) {
        int i = tid + 256 * j;
        float a = p0[i];
        F[i] = a + wz * (p1[i] - a);
    }
    __syncthreads();

    int w = tid >> 5, lane = tid & 31;

    #pragma unroll
    for (int j = 0; j < 16; ++j) {
        int yo = j * 8 + w;
        float py = (float)yo * S;
        int y0 = (int)py;
        int y1 = min(y0 + 1, 31);
        float wy = py - (float)y0;
        float a = F[y0 * 32 + lane];
        float b = F[y1 * 32 + lane];
        R[yo][lane] = a + wy * (b - a);
    }
    __syncthreads();

    int   x0[4], x1[4];
    float wx[4];
    #pragma unroll
    for (int j = 0; j < 4; ++j) {
        int xo = lane * 4 + j;
        float px = (float)xo * S;
        x0[j] = (int)px;
        x1[j] = min(x0[j] + 1, 31);
        wx[j] = px - (float)x0[j];
    }

    size_t obase = ((size_t)(c * 128 + zo)) * 16384;
    #pragma unroll
    for (int it = 0; it < 16; ++it) {
        int yo = it * 8 + w;
        const float* Rr = &R[yo][0];
        float4 o;
        #pragma unroll
        for (int j = 0; j < 4; ++j) {
            float r0 = Rr[x0[j]];
            (&o.x)[j] = r0 + wx[j] * (Rr[x1[j]] - r0);
        }
        __stcs((float4*)(out + obase + (size_t)yo * 128 + lane * 4), o);
    }
}

// ---------------- launch --------------------------------------------------------
extern "C" void kernel_launch(void* const* d_in, const int* in_sizes, int n_in,
                              void* d_out, int out_size)
{
    const float* x       = (const float*)d_in[0];
    const float* w_patch = (const float*)d_in[1];
    const float* b_patch = (const float*)d_in[2];
    const float* pos     = (const float*)d_in[3];

    conv_pos_kernel<<<NTOK / 32, 256>>>(x, w_patch, b_patch, pos);

    fused_attn_kernel<<<NBLK, 512>>>(
        (const float*)d_in[4],  (const float*)d_in[5],
        (const float*)d_in[6],  (const float*)d_in[7],
        (const float*)d_in[8],  (const float*)d_in[9],
        (const float*)d_in[10], (const float*)d_in[11],
        (const float*)d_in[12], (const float*)d_in[13],
        (const float*)d_in[14], (const float*)d_in[15]);

    upsample_kernel<<<dim3(128, 64), 256>>>((float*)d_out);
}